// round 1
// baseline (speedup 1.0000x reference)
#include <cuda_runtime.h>
#include <cstdint>
#include <math.h>

#define TOKENS 8192
#define HIDDEN 7168
#define NEXP   256
#define TOP_K  8

#define BM 64
#define BN 128
#define BK 16
#define NTHREADS 256
#define ASTRIDE 20    // BK + 4 : conflict-free A fragment reads
#define BSTRIDE 132   // BN + 4 : 16B-aligned rows, mild 2-way conflict
#define KT (HIDDEN / BK)   // 448

// scratch for logits (no cudaMalloc allowed)
__device__ float g_logits[TOKENS * (size_t)NEXP];

__device__ __forceinline__ uint32_t cvt_tf32(float x) {
    uint32_t r;
    asm("cvt.rna.tf32.f32 %0, %1;" : "=r"(r) : "f"(x));
    return r;
}

__device__ __forceinline__ uint32_t smem_u32(const void* p) {
    return (uint32_t)__cvta_generic_to_shared(p);
}

__device__ __forceinline__ void cp_async16(uint32_t s, const void* g) {
    asm volatile("cp.async.cg.shared.global [%0], [%1], 16;\n" :: "r"(s), "l"(g));
}

__device__ __forceinline__ void mma_tf32(float* c, const uint32_t* a, const uint32_t* b) {
    asm volatile(
        "mma.sync.aligned.m16n8k8.row.col.f32.tf32.tf32.f32 "
        "{%0,%1,%2,%3}, {%4,%5,%6,%7}, {%8,%9}, {%0,%1,%2,%3};\n"
        : "+f"(c[0]), "+f"(c[1]), "+f"(c[2]), "+f"(c[3])
        : "r"(a[0]), "r"(a[1]), "r"(a[2]), "r"(a[3]), "r"(b[0]), "r"(b[1]));
}

// ---------------------------------------------------------------------------
// GEMM: logits[8192,256] = A[8192,7168] * B[7168,256], tf32 tensor cores
// ---------------------------------------------------------------------------
__global__ __launch_bounds__(NTHREADS) void gemm_tf32_kernel(
    const float* __restrict__ A, const float* __restrict__ B)
{
    __shared__ float As[2][BM * ASTRIDE];
    __shared__ float Bs[2][BK * BSTRIDE];

    const int tid  = threadIdx.x;
    const int wid  = tid >> 5;
    const int lane = tid & 31;
    const int warp_m = wid >> 2;   // 0..1
    const int warp_n = wid & 3;    // 0..3
    const int brow = blockIdx.y * BM;
    const int bcol = blockIdx.x * BN;

    // global->smem load indices
    const int ar = tid >> 2;              // A tile row 0..63
    const int ac = (tid & 3) * 4;         // A tile col (float4)

    float c[2][4][4];
    #pragma unroll
    for (int mt = 0; mt < 2; mt++)
        #pragma unroll
        for (int nt = 0; nt < 4; nt++)
            #pragma unroll
            for (int i = 0; i < 4; i++) c[mt][nt][i] = 0.f;

    auto load_stage = [&](int kt, int buf) {
        const int k0 = kt * BK;
        // A: 64x16 floats = 256 float4, 1 per thread
        cp_async16(smem_u32(&As[buf][ar * ASTRIDE + ac]),
                   A + (size_t)(brow + ar) * HIDDEN + k0 + ac);
        // B: 16x128 floats = 512 float4, 2 per thread
        #pragma unroll
        for (int j = 0; j < 2; j++) {
            int i  = tid + j * 256;
            int r  = i >> 5;          // 0..15
            int cs = i & 31;          // 0..31
            cp_async16(smem_u32(&Bs[buf][r * BSTRIDE + cs * 4]),
                       B + (size_t)(k0 + r) * NEXP + bcol + cs * 4);
        }
        asm volatile("cp.async.commit_group;\n" ::: "memory");
    };

    load_stage(0, 0);

    for (int kt = 0; kt < KT; kt++) {
        const int buf = kt & 1;
        if (kt + 1 < KT) {
            load_stage(kt + 1, buf ^ 1);
            asm volatile("cp.async.wait_group 1;\n" ::: "memory");
        } else {
            asm volatile("cp.async.wait_group 0;\n" ::: "memory");
        }
        __syncthreads();

        #pragma unroll
        for (int ks = 0; ks < 2; ks++) {
            const int kk = ks * 8;
            uint32_t afr[2][4];
            uint32_t bfr[4][2];
            #pragma unroll
            for (int mt = 0; mt < 2; mt++) {
                int m0 = warp_m * 32 + mt * 16 + (lane >> 2);
                int cc = kk + (lane & 3);
                afr[mt][0] = cvt_tf32(As[buf][m0 * ASTRIDE + cc]);
                afr[mt][1] = cvt_tf32(As[buf][(m0 + 8) * ASTRIDE + cc]);
                afr[mt][2] = cvt_tf32(As[buf][m0 * ASTRIDE + cc + 4]);
                afr[mt][3] = cvt_tf32(As[buf][(m0 + 8) * ASTRIDE + cc + 4]);
            }
            #pragma unroll
            for (int nt = 0; nt < 4; nt++) {
                int n0 = warp_n * 32 + nt * 8 + (lane >> 2);
                int kr = kk + (lane & 3);
                bfr[nt][0] = cvt_tf32(Bs[buf][kr * BSTRIDE + n0]);
                bfr[nt][1] = cvt_tf32(Bs[buf][(kr + 4) * BSTRIDE + n0]);
            }
            #pragma unroll
            for (int mt = 0; mt < 2; mt++)
                #pragma unroll
                for (int nt = 0; nt < 4; nt++)
                    mma_tf32(c[mt][nt], afr[mt], bfr[nt]);
        }
        __syncthreads();
    }

    // epilogue: store logits
    #pragma unroll
    for (int mt = 0; mt < 2; mt++) {
        #pragma unroll
        for (int nt = 0; nt < 4; nt++) {
            int row = brow + warp_m * 32 + mt * 16 + (lane >> 2);
            int col = bcol + warp_n * 32 + nt * 8 + (lane & 3) * 2;
            float2 v0 = make_float2(c[mt][nt][0], c[mt][nt][1]);
            float2 v1 = make_float2(c[mt][nt][2], c[mt][nt][3]);
            *(float2*)&g_logits[(size_t)row * NEXP + col]       = v0;
            *(float2*)&g_logits[(size_t)(row + 8) * NEXP + col] = v1;
        }
    }
}

// ---------------------------------------------------------------------------
// Routing: sigmoid + bias, group top-2 sums, top-4 groups, top-8 experts,
// renormalize * 2.5. One warp per token.
// ---------------------------------------------------------------------------
__global__ __launch_bounds__(256) void route_kernel(
    const float* __restrict__ bias, float* __restrict__ out)
{
    const int lane  = threadIdx.x & 31;
    const int token = blockIdx.x * 8 + (threadIdx.x >> 5);
    if (token >= TOKENS) return;

    const float* lrow = g_logits + (size_t)token * NEXP;

    // lane handles experts [lane*8, lane*8+8); group = lane/4 (32 experts/group)
    float s[8];
    #pragma unroll
    for (int i = 0; i < 8; i++) {
        int e = lane * 8 + i;
        float logit = lrow[e];
        float sc = 1.f / (1.f + expf(-logit));
        s[i] = sc + __ldg(&bias[e]);
    }

    // per-lane top-2
    float m1 = -INFINITY, m2 = -INFINITY;
    #pragma unroll
    for (int i = 0; i < 8; i++) {
        float v = s[i];
        if (v > m1) { m2 = m1; m1 = v; }
        else if (v > m2) { m2 = v; }
    }
    // merge top-2 across the 4 lanes of the group (xor 1, 2 stay in-group)
    #pragma unroll
    for (int off = 1; off <= 2; off <<= 1) {
        float o1 = __shfl_xor_sync(0xffffffffu, m1, off);
        float o2 = __shfl_xor_sync(0xffffffffu, m2, off);
        float hi = fmaxf(m1, o1);
        float lo = fmaxf(fminf(m1, o1), fmaxf(m2, o2));
        m1 = hi; m2 = lo;
    }
    float gsum = m1 + m2;

    // gather all 8 group sums
    float gs[8];
    #pragma unroll
    for (int g = 0; g < 8; g++)
        gs[g] = __shfl_sync(0xffffffffu, gsum, g * 4);

    // rank of my group; selected if rank < 4 (lowest index wins ties)
    const int myg = lane >> 2;
    int rank = 0;
    #pragma unroll
    for (int h = 0; h < 8; h++)
        if (gs[h] > gs[myg] || (gs[h] == gs[myg] && h < myg)) rank++;
    const bool sel = rank < 4;

    float vals[8];
    #pragma unroll
    for (int i = 0; i < 8; i++) vals[i] = sel ? s[i] : 0.f;

    // iterative top-8 with lowest-global-index tie-break (matches lax.top_k)
    float w[TOP_K];
    #pragma unroll
    for (int t = 0; t < TOP_K; t++) {
        float bv = vals[0];
        int bi = 0;
        #pragma unroll
        for (int i = 1; i < 8; i++)
            if (vals[i] > bv) { bv = vals[i]; bi = i; }
        int bidx = lane * 8 + bi;
        #pragma unroll
        for (int off = 16; off >= 1; off >>= 1) {
            float ov = __shfl_xor_sync(0xffffffffu, bv, off);
            int   oi = __shfl_xor_sync(0xffffffffu, bidx, off);
            if (ov > bv || (ov == bv && oi < bidx)) { bv = ov; bidx = oi; }
        }
        w[t] = bv;
        if ((bidx >> 3) == lane) vals[bidx & 7] = -INFINITY;
    }

    float denom = 1e-20f;
    #pragma unroll
    for (int t = 0; t < TOP_K; t++) denom += w[t];
    const float scale = 2.5f / denom;

    if (lane == 0) {
        #pragma unroll
        for (int t = 0; t < TOP_K; t++)
            out[(size_t)token * TOP_K + t] = w[t] * scale;
    }
}

// ---------------------------------------------------------------------------
extern "C" void kernel_launch(void* const* d_in, const int* in_sizes, int n_in,
                              void* d_out, int out_size)
{
    (void)in_sizes; (void)n_in; (void)out_size;
    const float* hs   = (const float*)d_in[0];  // [8192, 7168]
    const float* W    = (const float*)d_in[1];  // [7168, 256]
    const float* bias = (const float*)d_in[2];  // [256]
    float* out = (float*)d_out;                 // [8192, 8]

    dim3 grid(NEXP / BN, TOKENS / BM);          // (2, 128)
    gemm_tf32_kernel<<<grid, NTHREADS>>>(hs, W);
    route_kernel<<<TOKENS / 8, 256>>>(bias, out);
}

// round 3
// speedup vs baseline: 1.4747x; 1.4747x over previous
#include <cuda_runtime.h>
#include <cstdint>
#include <math.h>

#define TOKENS 8192
#define HIDDEN 7168
#define NEXP   256
#define TOP_K  8

// ---------------- GEMM config (mma.sync tf32 — tcgen05 not reachable via compute_103) --
#define BM 128
#define BN 128
#define BK 32
#define STAGES 3
#define KT_ITERS (HIDDEN / BK)     // 224
#define NTHREADS 256
#define ASTRIDE 36                 // banks (4r+c) all distinct  -> conflict-free A reads
#define BSTRIDE 136                // banks (8k+n) all distinct  -> conflict-free B reads
#define A_FLOATS (BM * ASTRIDE)    // 4608
#define B_FLOATS (BK * BSTRIDE)    // 4352
#define STAGE_FLOATS (A_FLOATS + B_FLOATS)
#define SMEM_DYN (STAGES * STAGE_FLOATS * 4)   // 107520 B

// scratch for logits (no cudaMalloc allowed)
__device__ float g_logits[(size_t)TOKENS * NEXP];

__device__ __forceinline__ uint32_t smem_u32(const void* p) {
    uint32_t a;
    asm("{ .reg .u64 t; cvta.to.shared.u64 t, %1; cvt.u32.u64 %0, t; }" : "=r"(a) : "l"(p));
    return a;
}
__device__ __forceinline__ void cp_async16(uint32_t s, const void* g) {
    asm volatile("cp.async.cg.shared.global [%0], [%1], 16;\n" :: "r"(s), "l"(g));
}
__device__ __forceinline__ void mma_tf32(float* c, const uint32_t* a, const uint32_t* b) {
    asm volatile(
        "mma.sync.aligned.m16n8k8.row.col.f32.tf32.tf32.f32 "
        "{%0,%1,%2,%3}, {%4,%5,%6,%7}, {%8,%9}, {%0,%1,%2,%3};\n"
        : "+f"(c[0]), "+f"(c[1]), "+f"(c[2]), "+f"(c[3])
        : "r"(a[0]), "r"(a[1]), "r"(a[2]), "r"(a[3]), "r"(b[0]), "r"(b[1]));
}

// ---------------------------------------------------------------------------
// GEMM: g_logits[8192,256] = A[8192,7168] * B[7168,256]
// 128 CTAs (one wave), 8 warps (2x4), warp tile 64x32, BK=32, 3-stage cp.async
// ---------------------------------------------------------------------------
__global__ __launch_bounds__(NTHREADS, 1) void gemm_kernel(
    const float* __restrict__ A, const float* __restrict__ B)
{
    extern __shared__ float smem[];

    const int tid    = threadIdx.x;
    const int wid    = tid >> 5;
    const int lane   = tid & 31;
    const int warp_m = wid >> 2;   // 0..1 -> 64 rows each
    const int warp_n = wid & 3;    // 0..3 -> 32 cols each
    const int brow   = blockIdx.y * BM;
    const int bcol   = blockIdx.x * BN;

    // per-thread load slots (4 x 16B for A, 4 x 16B for B per stage)
    const float* agp[4]; uint32_t aof[4];
    const float* bgp[4]; uint32_t bof[4];
    #pragma unroll
    for (int j = 0; j < 4; j++) {
        int i = tid + j * 256;          // A: 128 rows x 8 chunks of 4 floats
        int r = i >> 3, c = i & 7;
        aof[j] = (uint32_t)(r * ASTRIDE + c * 4) * 4u;
        agp[j] = A + (size_t)(brow + r) * HIDDEN + c * 4;
    }
    #pragma unroll
    for (int j = 0; j < 4; j++) {
        int i = tid + j * 256;          // B: 32 rows x 32 chunks of 4 floats
        int r = i >> 5, cs = i & 31;
        bof[j] = (uint32_t)(A_FLOATS + r * BSTRIDE + cs * 4) * 4u;
        bgp[j] = B + (size_t)r * NEXP + bcol + cs * 4;
    }
    const uint32_t smem_base = smem_u32(smem);

    auto load_stage = [&](int kt) {
        const uint32_t sbase = smem_base + (uint32_t)(kt % STAGES) * (STAGE_FLOATS * 4);
        const int koff = kt * BK;
        #pragma unroll
        for (int j = 0; j < 4; j++) cp_async16(sbase + aof[j], agp[j] + koff);
        #pragma unroll
        for (int j = 0; j < 4; j++) cp_async16(sbase + bof[j], bgp[j] + (size_t)koff * NEXP);
        asm volatile("cp.async.commit_group;\n" ::: "memory");
    };

    float c[2][4][4];
    #pragma unroll
    for (int mt = 0; mt < 2; mt++)
        #pragma unroll
        for (int nt = 0; nt < 4; nt++)
            #pragma unroll
            for (int i = 0; i < 4; i++) c[mt][nt][i] = 0.f;
    // accum for upper/lower M halves of the 64-row warp tile
    float c2[2][4][4];
    #pragma unroll
    for (int mt = 0; mt < 2; mt++)
        #pragma unroll
        for (int nt = 0; nt < 4; nt++)
            #pragma unroll
            for (int i = 0; i < 4; i++) c2[mt][nt][i] = 0.f;

    load_stage(0);
    load_stage(1);

    const int arow0 = warp_m * 64 + (lane >> 2);   // + mt*16, +8
    const int bcol0 = warp_n * 32 + (lane >> 2);   // + nt*8
    const int ak    = lane & 3;

    for (int kt = 0; kt < KT_ITERS; kt++) {
        if (kt == KT_ITERS - 1)
            asm volatile("cp.async.wait_group 0;\n" ::: "memory");
        else
            asm volatile("cp.async.wait_group 1;\n" ::: "memory");
        __syncthreads();

        const float* As = smem + (size_t)(kt % STAGES) * STAGE_FLOATS;
        const float* Bs = As + A_FLOATS;

        #pragma unroll
        for (int ks = 0; ks < 4; ks++) {
            const int kk = ks * 8;
            uint32_t afr[4][4];     // 4 m-subtiles (16 rows each) covering 64 rows
            uint32_t bfr[4][2];
            #pragma unroll
            for (int mt = 0; mt < 4; mt++) {
                const int m0 = arow0 + mt * 16;
                const int cc = kk + ak;
                afr[mt][0] = __float_as_uint(As[m0 * ASTRIDE + cc]);
                afr[mt][1] = __float_as_uint(As[(m0 + 8) * ASTRIDE + cc]);
                afr[mt][2] = __float_as_uint(As[m0 * ASTRIDE + cc + 4]);
                afr[mt][3] = __float_as_uint(As[(m0 + 8) * ASTRIDE + cc + 4]);
            }
            #pragma unroll
            for (int nt = 0; nt < 4; nt++) {
                const int n0 = bcol0 + nt * 8;
                const int kr = kk + ak;
                bfr[nt][0] = __float_as_uint(Bs[kr * BSTRIDE + n0]);
                bfr[nt][1] = __float_as_uint(Bs[(kr + 4) * BSTRIDE + n0]);
            }
            #pragma unroll
            for (int nt = 0; nt < 4; nt++) {
                mma_tf32(c[0][nt],  afr[0], bfr[nt]);
                mma_tf32(c[1][nt],  afr[1], bfr[nt]);
                mma_tf32(c2[0][nt], afr[2], bfr[nt]);
                mma_tf32(c2[1][nt], afr[3], bfr[nt]);
            }
        }
        __syncthreads();
        if (kt + 2 < KT_ITERS) load_stage(kt + 2);
    }

    // epilogue
    #pragma unroll
    for (int half = 0; half < 2; half++) {
        #pragma unroll
        for (int mt = 0; mt < 2; mt++) {
            #pragma unroll
            for (int nt = 0; nt < 4; nt++) {
                float* cc = half ? c2[mt][nt] : c[mt][nt];
                int row = brow + warp_m * 64 + (half * 2 + mt) * 16 + (lane >> 2);
                int col = bcol + warp_n * 32 + nt * 8 + (lane & 3) * 2;
                *(float2*)&g_logits[(size_t)row * NEXP + col] =
                    make_float2(cc[0], cc[1]);
                *(float2*)&g_logits[(size_t)(row + 8) * NEXP + col] =
                    make_float2(cc[2], cc[3]);
            }
        }
    }
}

// ---------------------------------------------------------------------------
// Routing: sigmoid + bias, group top-2 sums, top-4 groups, top-8 experts,
// renormalize * 2.5. One warp per token.
// ---------------------------------------------------------------------------
__global__ __launch_bounds__(256) void route_kernel(
    const float* __restrict__ bias, float* __restrict__ out)
{
    const int lane  = threadIdx.x & 31;
    const int token = blockIdx.x * 8 + (threadIdx.x >> 5);
    if (token >= TOKENS) return;

    const float* lrow = g_logits + (size_t)token * NEXP;

    float s[8];
    #pragma unroll
    for (int i = 0; i < 8; i++) {
        int e = lane * 8 + i;
        float logit = lrow[e];
        float sc = 1.f / (1.f + expf(-logit));
        s[i] = sc + __ldg(&bias[e]);
    }

    float m1 = -INFINITY, m2 = -INFINITY;
    #pragma unroll
    for (int i = 0; i < 8; i++) {
        float v = s[i];
        if (v > m1) { m2 = m1; m1 = v; }
        else if (v > m2) { m2 = v; }
    }
    #pragma unroll
    for (int off = 1; off <= 2; off <<= 1) {
        float o1 = __shfl_xor_sync(0xffffffffu, m1, off);
        float o2 = __shfl_xor_sync(0xffffffffu, m2, off);
        float hi = fmaxf(m1, o1);
        float lo = fmaxf(fminf(m1, o1), fmaxf(m2, o2));
        m1 = hi; m2 = lo;
    }
    float gsum = m1 + m2;

    float gs[8];
    #pragma unroll
    for (int g = 0; g < 8; g++)
        gs[g] = __shfl_sync(0xffffffffu, gsum, g * 4);

    const int myg = lane >> 2;
    int rank = 0;
    #pragma unroll
    for (int h = 0; h < 8; h++)
        if (gs[h] > gs[myg] || (gs[h] == gs[myg] && h < myg)) rank++;
    const bool sel = rank < 4;

    float vals[8];
    #pragma unroll
    for (int i = 0; i < 8; i++) vals[i] = sel ? s[i] : 0.f;

    float w[TOP_K];
    #pragma unroll
    for (int t = 0; t < TOP_K; t++) {
        float bv = vals[0];
        int bi = 0;
        #pragma unroll
        for (int i = 1; i < 8; i++)
            if (vals[i] > bv) { bv = vals[i]; bi = i; }
        int bidx = lane * 8 + bi;
        #pragma unroll
        for (int off = 16; off >= 1; off >>= 1) {
            float ov = __shfl_xor_sync(0xffffffffu, bv, off);
            int   oi = __shfl_xor_sync(0xffffffffu, bidx, off);
            if (ov > bv || (ov == bv && oi < bidx)) { bv = ov; bidx = oi; }
        }
        w[t] = bv;
        if ((bidx >> 3) == lane) vals[bidx & 7] = -INFINITY;
    }

    float denom = 1e-20f;
    #pragma unroll
    for (int t = 0; t < TOP_K; t++) denom += w[t];
    const float scale = 2.5f / denom;

    if (lane == 0) {
        #pragma unroll
        for (int t = 0; t < TOP_K; t++)
            out[(size_t)token * TOP_K + t] = w[t] * scale;
    }
}

// ---------------------------------------------------------------------------
extern "C" void kernel_launch(void* const* d_in, const int* in_sizes, int n_in,
                              void* d_out, int out_size)
{
    (void)in_sizes; (void)n_in; (void)out_size;
    const float* hs   = (const float*)d_in[0];  // [8192, 7168]
    const float* W    = (const float*)d_in[1];  // [7168, 256]
    const float* bias = (const float*)d_in[2];  // [256]
    float* out = (float*)d_out;                 // [8192, 8]

    cudaFuncSetAttribute(gemm_kernel, cudaFuncAttributeMaxDynamicSharedMemorySize, SMEM_DYN);

    dim3 grid(NEXP / BN, TOKENS / BM);          // (2, 64) = 128 CTAs, one wave
    gemm_kernel<<<grid, NTHREADS, SMEM_DYN>>>(hs, W);
    route_kernel<<<TOKENS / 8, 256>>>(bias, out);
}

// round 4
// speedup vs baseline: 1.5261x; 1.0348x over previous
#include <cuda_runtime.h>
#include <cstdint>
#include <math.h>

#define TOKENS 8192
#define HIDDEN 7168
#define NEXP   256
#define TOP_K  8

// ---------------- GEMM config: mma.sync tf32, fine tiles for 148-SM fill -----
#define BM 64
#define BN 64
#define BK 32
#define STAGES 3
#define KT_ITERS (HIDDEN / BK)     // 224
#define NTHREADS 64                // 2 warps, each 64x32
#define ASTRIDE 36                 // banks (4r+k) all distinct
#define BSTRIDE 72                 // banks (8k+n) all distinct
#define A_FLOATS (BM * ASTRIDE)    // 2304
#define B_FLOATS (BK * BSTRIDE)    // 2304
#define STAGE_FLOATS (A_FLOATS + B_FLOATS)      // 4608
#define SMEM_DYN (STAGES * STAGE_FLOATS * 4)    // 55296 B -> 4 CTAs/SM

// scratch for logits (no cudaMalloc allowed)
__device__ float g_logits[(size_t)TOKENS * NEXP];

__device__ __forceinline__ uint32_t smem_u32(const void* p) {
    uint32_t a;
    asm("{ .reg .u64 t; cvta.to.shared.u64 t, %1; cvt.u32.u64 %0, t; }" : "=r"(a) : "l"(p));
    return a;
}
__device__ __forceinline__ void cp_async16(uint32_t s, const void* g) {
    asm volatile("cp.async.cg.shared.global [%0], [%1], 16;\n" :: "r"(s), "l"(g));
}
__device__ __forceinline__ void mma_tf32(float* c, const uint32_t* a, const uint32_t* b) {
    asm volatile(
        "mma.sync.aligned.m16n8k8.row.col.f32.tf32.tf32.f32 "
        "{%0,%1,%2,%3}, {%4,%5,%6,%7}, {%8,%9}, {%0,%1,%2,%3};\n"
        : "+f"(c[0]), "+f"(c[1]), "+f"(c[2]), "+f"(c[3])
        : "r"(a[0]), "r"(a[1]), "r"(a[2]), "r"(a[3]), "r"(b[0]), "r"(b[1]));
}

// ---------------------------------------------------------------------------
// GEMM: g_logits[8192,256] = A[8192,7168] * B[7168,256]
// 512 CTAs (64x64 tile, 2 warps of 64x32), BK=32, 3-stage cp.async,
// single __syncthreads per k-tile.
// ---------------------------------------------------------------------------
__global__ __launch_bounds__(NTHREADS, 4) void gemm_kernel(
    const float* __restrict__ A, const float* __restrict__ B)
{
    extern __shared__ float smem[];

    const int tid  = threadIdx.x;
    const int wid  = tid >> 5;          // 0..1 -> 32-col slice
    const int lane = tid & 31;
    const int brow = blockIdx.y * BM;   // 128 m-blocks
    const int bcol = blockIdx.x * BN;   // 4 n-blocks (fastest -> A shared in L2)

    // per-thread load slots: A 512 chunks (8/thread), B 512 chunks (8/thread)
    const float* agp[8]; uint32_t aof[8];
    const float* bgp[8]; uint32_t bof[8];
    #pragma unroll
    for (int j = 0; j < 8; j++) {
        int i = tid + j * 64;           // A: 64 rows x 8 chunks of 16B
        int r = i >> 3, c = i & 7;
        aof[j] = (uint32_t)(r * ASTRIDE + c * 4) * 4u;
        agp[j] = A + (size_t)(brow + r) * HIDDEN + c * 4;
    }
    #pragma unroll
    for (int j = 0; j < 8; j++) {
        int i = tid + j * 64;           // B: 32 rows x 16 chunks of 16B
        int r = i >> 4, c = i & 15;
        bof[j] = (uint32_t)(A_FLOATS + r * BSTRIDE + c * 4) * 4u;
        bgp[j] = B + (size_t)r * NEXP + bcol + c * 4;
    }
    const uint32_t smem_base = smem_u32(smem);

    auto load_stage = [&](int kt) {
        const uint32_t sbase = smem_base + (uint32_t)(kt % STAGES) * (STAGE_FLOATS * 4);
        const int koff = kt * BK;
        #pragma unroll
        for (int j = 0; j < 8; j++) cp_async16(sbase + aof[j], agp[j] + koff);
        #pragma unroll
        for (int j = 0; j < 8; j++) cp_async16(sbase + bof[j], bgp[j] + (size_t)koff * NEXP);
        asm volatile("cp.async.commit_group;\n" ::: "memory");
    };

    float acc[4][4][4];   // mt (16-row subtiles) x nt (8-col subtiles) x 4
    #pragma unroll
    for (int mt = 0; mt < 4; mt++)
        #pragma unroll
        for (int nt = 0; nt < 4; nt++)
            #pragma unroll
            for (int i = 0; i < 4; i++) acc[mt][nt][i] = 0.f;

    load_stage(0);
    load_stage(1);

    const int arow0 = lane >> 2;               // + mt*16, +8
    const int bcol0 = wid * 32 + (lane >> 2);  // + nt*8
    const int ak    = lane & 3;

    for (int kt = 0; kt < KT_ITERS; kt++) {
        if (kt == KT_ITERS - 1)
            asm volatile("cp.async.wait_group 0;\n" ::: "memory");
        else
            asm volatile("cp.async.wait_group 1;\n" ::: "memory");
        __syncthreads();   // single barrier per kt: also protects buffer reuse

        if (kt + 2 < KT_ITERS) load_stage(kt + 2);

        const float* As = smem + (size_t)(kt % STAGES) * STAGE_FLOATS;
        const float* Bs = As + A_FLOATS;

        #pragma unroll
        for (int ks = 0; ks < 4; ks++) {
            const int kk = ks * 8;
            uint32_t afr[4][4];
            uint32_t bfr[4][2];
            #pragma unroll
            for (int mt = 0; mt < 4; mt++) {
                const int m0 = arow0 + mt * 16;
                const int cc = kk + ak;
                afr[mt][0] = __float_as_uint(As[m0 * ASTRIDE + cc]);
                afr[mt][1] = __float_as_uint(As[(m0 + 8) * ASTRIDE + cc]);
                afr[mt][2] = __float_as_uint(As[m0 * ASTRIDE + cc + 4]);
                afr[mt][3] = __float_as_uint(As[(m0 + 8) * ASTRIDE + cc + 4]);
            }
            #pragma unroll
            for (int nt = 0; nt < 4; nt++) {
                const int n0 = bcol0 + nt * 8;
                const int kr = kk + ak;
                bfr[nt][0] = __float_as_uint(Bs[kr * BSTRIDE + n0]);
                bfr[nt][1] = __float_as_uint(Bs[(kr + 4) * BSTRIDE + n0]);
            }
            #pragma unroll
            for (int mt = 0; mt < 4; mt++)
                #pragma unroll
                for (int nt = 0; nt < 4; nt++)
                    mma_tf32(acc[mt][nt], afr[mt], bfr[nt]);
        }
    }

    // epilogue
    #pragma unroll
    for (int mt = 0; mt < 4; mt++) {
        #pragma unroll
        for (int nt = 0; nt < 4; nt++) {
            int row = brow + mt * 16 + (lane >> 2);
            int col = bcol + wid * 32 + nt * 8 + (lane & 3) * 2;
            *(float2*)&g_logits[(size_t)row * NEXP + col] =
                make_float2(acc[mt][nt][0], acc[mt][nt][1]);
            *(float2*)&g_logits[(size_t)(row + 8) * NEXP + col] =
                make_float2(acc[mt][nt][2], acc[mt][nt][3]);
        }
    }
}

// ---------------------------------------------------------------------------
// Routing: sigmoid + bias, group top-2 sums, top-4 groups, top-8 experts,
// renormalize * 2.5. One warp per token.
// ---------------------------------------------------------------------------
__global__ __launch_bounds__(256) void route_kernel(
    const float* __restrict__ bias, float* __restrict__ out)
{
    const int lane  = threadIdx.x & 31;
    const int token = blockIdx.x * 8 + (threadIdx.x >> 5);
    if (token >= TOKENS) return;

    const float* lrow = g_logits + (size_t)token * NEXP;

    float s[8];
    #pragma unroll
    for (int i = 0; i < 8; i++) {
        int e = lane * 8 + i;
        float logit = lrow[e];
        float sc = 1.f / (1.f + expf(-logit));
        s[i] = sc + __ldg(&bias[e]);
    }

    float m1 = -INFINITY, m2 = -INFINITY;
    #pragma unroll
    for (int i = 0; i < 8; i++) {
        float v = s[i];
        if (v > m1) { m2 = m1; m1 = v; }
        else if (v > m2) { m2 = v; }
    }
    #pragma unroll
    for (int off = 1; off <= 2; off <<= 1) {
        float o1 = __shfl_xor_sync(0xffffffffu, m1, off);
        float o2 = __shfl_xor_sync(0xffffffffu, m2, off);
        float hi = fmaxf(m1, o1);
        float lo = fmaxf(fminf(m1, o1), fmaxf(m2, o2));
        m1 = hi; m2 = lo;
    }
    float gsum = m1 + m2;

    float gs[8];
    #pragma unroll
    for (int g = 0; g < 8; g++)
        gs[g] = __shfl_sync(0xffffffffu, gsum, g * 4);

    const int myg = lane >> 2;
    int rank = 0;
    #pragma unroll
    for (int h = 0; h < 8; h++)
        if (gs[h] > gs[myg] || (gs[h] == gs[myg] && h < myg)) rank++;
    const bool sel = rank < 4;

    float vals[8];
    #pragma unroll
    for (int i = 0; i < 8; i++) vals[i] = sel ? s[i] : 0.f;

    float w[TOP_K];
    #pragma unroll
    for (int t = 0; t < TOP_K; t++) {
        float bv = vals[0];
        int bi = 0;
        #pragma unroll
        for (int i = 1; i < 8; i++)
            if (vals[i] > bv) { bv = vals[i]; bi = i; }
        int bidx = lane * 8 + bi;
        #pragma unroll
        for (int off = 16; off >= 1; off >>= 1) {
            float ov = __shfl_xor_sync(0xffffffffu, bv, off);
            int   oi = __shfl_xor_sync(0xffffffffu, bidx, off);
            if (ov > bv || (ov == bv && oi < bidx)) { bv = ov; bidx = oi; }
        }
        w[t] = bv;
        if ((bidx >> 3) == lane) vals[bidx & 7] = -INFINITY;
    }

    float denom = 1e-20f;
    #pragma unroll
    for (int t = 0; t < TOP_K; t++) denom += w[t];
    const float scale = 2.5f / denom;

    if (lane == 0) {
        #pragma unroll
        for (int t = 0; t < TOP_K; t++)
            out[(size_t)token * TOP_K + t] = w[t] * scale;
    }
}

// ---------------------------------------------------------------------------
extern "C" void kernel_launch(void* const* d_in, const int* in_sizes, int n_in,
                              void* d_out, int out_size)
{
    (void)in_sizes; (void)n_in; (void)out_size;
    const float* hs   = (const float*)d_in[0];  // [8192, 7168]
    const float* W    = (const float*)d_in[1];  // [7168, 256]
    const float* bias = (const float*)d_in[2];  // [256]
    float* out = (float*)d_out;                 // [8192, 8]

    cudaFuncSetAttribute(gemm_kernel, cudaFuncAttributeMaxDynamicSharedMemorySize, SMEM_DYN);

    dim3 grid(NEXP / BN, TOKENS / BM);          // (4, 128) = 512 CTAs
    gemm_kernel<<<grid, NTHREADS, SMEM_DYN>>>(hs, W);
    route_kernel<<<TOKENS / 8, 256>>>(bias, out);
}